// round 1
// baseline (speedup 1.0000x reference)
#include <cuda_runtime.h>

// RNN_49684181680264 : Elman RNN forward
//   h_t = tanh(h_{t-1} @ Whh + b_hh + x_t * Wxh + b_xh),  out = h_T @ Wout + b_out
// B=16384, T=1024, H=32.
// Strategy: one thread per batch row. h lives in 32 registers. Whh broadcast
// from SMEM (ld.shared.v2.u64 -> LDS.128, all lanes same address = broadcast).
// MACs via packed fp32 fma.rn.f32x2 (FFMA2) -> 2x fp32 FMA throughput.
// x staged through SMEM in [128 x 32] tiles (coalesced global loads, padded
// stride-33 rows to avoid bank conflicts on the per-thread strided read).

#define RNN_B 16384
#define RNN_T 1024
#define RNN_H 32
#define CTA_B 128   // batch rows (=threads) per CTA
#define TT    32    // time-tile staged in smem

typedef unsigned long long u64;

__device__ __forceinline__ void fma2(u64 &d, u64 a, u64 b) {
    // d = a * b + d  (packed 2x fp32)
    asm("fma.rn.f32x2 %0, %1, %2, %0;" : "+l"(d) : "l"(a), "l"(b));
}
__device__ __forceinline__ u64 bcast2(float s) {
    u64 d;
    asm("mov.b64 %0, {%1, %1};" : "=l"(d) : "f"(s));
    return d;
}
__device__ __forceinline__ void unpack2(u64 v, float &lo, float &hi) {
    asm("mov.b64 {%0, %1}, %2;" : "=f"(lo), "=f"(hi) : "l"(v));
}

// tanh(v) = sign(v) * (1 - e) / (1 + e),  e = exp(-2|v|).
// ex2/rcp approx: rel err ~2^-22 -> abs err on h ~1e-7, safe for the recurrence.
__device__ __forceinline__ float fast_tanh(float v) {
    const float n2log2e = -2.885390081777927f;  // -2 * log2(e)
    float ax = fabsf(v);
    float e, r;
    asm("ex2.approx.f32 %0, %1;" : "=f"(e) : "f"(ax * n2log2e));
    asm("rcp.approx.f32 %0, %1;" : "=f"(r) : "f"(1.0f + e));
    return copysignf((1.0f - e) * r, v);
}

__global__ __launch_bounds__(CTA_B, 1)
void rnn_fwd_kernel(const float* __restrict__ x,
                    const float* __restrict__ Wxh,
                    const float* __restrict__ b_xh,
                    const float* __restrict__ Whh,
                    const float* __restrict__ b_hh,
                    const float* __restrict__ Wout,
                    const float* __restrict__ b_out,
                    float* __restrict__ out)
{
    __shared__ __align__(16) float sW[RNN_H * RNN_H];  // Whh[k][j]
    __shared__ __align__(16) float sWxh[RNN_H];
    __shared__ __align__(16) float sBsum[RNN_H];       // b_xh + b_hh
    __shared__ __align__(16) float sWout[RNN_H];
    __shared__ float sX[CTA_B][TT + 1];                // padded: conflict-free

    const int tid = threadIdx.x;
    const int b0  = blockIdx.x * CTA_B;

    // ---- load weights into smem ----
    #pragma unroll
    for (int i = tid; i < RNN_H * RNN_H; i += CTA_B) sW[i] = Whh[i];
    if (tid < RNN_H) {
        sWxh[tid]  = Wxh[tid];               // Wxh shape (1,H)
        sBsum[tid] = b_xh[tid] + b_hh[tid];
        sWout[tid] = Wout[tid];              // Wout shape (H,1)
    }

    const ulonglong2* __restrict__ W2  = reinterpret_cast<const ulonglong2*>(sW);
    const ulonglong2* __restrict__ Bs2 = reinterpret_cast<const ulonglong2*>(sBsum);
    const ulonglong2* __restrict__ Wx2 = reinterpret_cast<const ulonglong2*>(sWxh);

    // ---- h state in registers ----
    float h[RNN_H];
    #pragma unroll
    for (int j = 0; j < RNN_H; j++) h[j] = 0.0f;

    const float* __restrict__ xrow = x + (size_t)(b0) * RNN_T;

    for (int t0 = 0; t0 < RNN_T; t0 += TT) {
        __syncthreads();
        // stage x tile: [CTA_B batches][TT timesteps], coalesced along t
        #pragma unroll
        for (int i = tid; i < CTA_B * TT; i += CTA_B) {
            int bl = i >> 5, tt = i & (TT - 1);
            sX[bl][tt] = xrow[(size_t)bl * RNN_T + t0 + tt];
        }
        __syncthreads();

        #pragma unroll 1
        for (int tt = 0; tt < TT; tt++) {
            float xv = sX[tid][tt];

            // acc[j] = bsum[j] + xv * Wxh[j]   (16 packed pairs)
            u64 acc[RNN_H / 2];
            {
                u64 xx = bcast2(xv);
                #pragma unroll
                for (int m = 0; m < 8; m++) {
                    ulonglong2 bb = Bs2[m];
                    ulonglong2 ww = Wx2[m];
                    acc[2 * m]     = bb.x;
                    acc[2 * m + 1] = bb.y;
                    fma2(acc[2 * m],     xx, ww.x);
                    fma2(acc[2 * m + 1], xx, ww.y);
                }
            }

            // acc[j] += sum_k h[k] * Whh[k][j]
            #pragma unroll
            for (int k = 0; k < RNN_H; k++) {
                u64 hk = bcast2(h[k]);
                const ulonglong2* row = W2 + k * 8;
                #pragma unroll
                for (int m = 0; m < 8; m++) {
                    ulonglong2 ww = row[m];
                    fma2(acc[2 * m],     hk, ww.x);
                    fma2(acc[2 * m + 1], hk, ww.y);
                }
            }

            // h = tanh(acc)
            #pragma unroll
            for (int p = 0; p < RNN_H / 2; p++) {
                float lo, hi;
                unpack2(acc[p], lo, hi);
                h[2 * p]     = fast_tanh(lo);
                h[2 * p + 1] = fast_tanh(hi);
            }
        }
    }

    // ---- epilogue: out[b] = h . Wout + b_out ----
    float o = b_out[0];
    #pragma unroll
    for (int j = 0; j < RNN_H; j++) o = fmaf(h[j], sWout[j], o);
    out[b0 + tid] = o;
}

extern "C" void kernel_launch(void* const* d_in, const int* in_sizes, int n_in,
                              void* d_out, int out_size)
{
    const float* x     = (const float*)d_in[0];
    const float* Wxh   = (const float*)d_in[1];
    const float* b_xh  = (const float*)d_in[2];
    const float* Whh   = (const float*)d_in[3];
    const float* b_hh  = (const float*)d_in[4];
    const float* Wout  = (const float*)d_in[5];
    const float* b_out = (const float*)d_in[6];
    float* out = (float*)d_out;

    dim3 grid(RNN_B / CTA_B);   // 128 CTAs
    dim3 blk(CTA_B);            // 128 threads, 1 batch row each
    rnn_fwd_kernel<<<grid, blk>>>(x, Wxh, b_xh, Whh, b_hh, Wout, b_out, out);
}

// round 2
// speedup vs baseline: 1.8728x; 1.8728x over previous
#include <cuda_runtime.h>

// RNN_49684181680264 : Elman RNN forward, B=16384, T=1024, H=32.
//   h_t = tanh(h_{t-1} @ Whh + b_hh + x_t * Wxh + b_xh);  out = h_T @ Wout + b_out
//
// R2 design: 4 threads per batch row (j-split 8 each) -> 65536 threads =
// 2048 warps = ~3.5 warps/SMSP (R1 had 0.87 -> all latency exposed, fma=8%).
// h exchanged per step with 24 shfl.bfly within each 4-lane group.
// MACs via packed fma.rn.f32x2 (2x fp32 FMA throughput). Whh broadcast from
// SMEM, 2x LDS.128 per k per thread. Registers ~<=128, no spills (R1: 255+spill).

#define RNN_B 16384
#define RNN_T 1024
#define RNN_H 32
#define CTA_THREADS 64          // 16 batch rows per CTA, 4 threads each
#define BATCH_PER_CTA (CTA_THREADS / 4)
#define TT 32                   // time tile staged in smem

typedef unsigned long long u64;

__device__ __forceinline__ void fma2(u64 &d, u64 a, u64 b) {
    asm("fma.rn.f32x2 %0, %1, %2, %0;" : "+l"(d) : "l"(a), "l"(b));
}
__device__ __forceinline__ u64 bcast2(float s) {
    u64 d; asm("mov.b64 %0, {%1, %1};" : "=l"(d) : "f"(s)); return d;
}
__device__ __forceinline__ u64 pack2(float lo, float hi) {
    u64 d; asm("mov.b64 %0, {%1, %2};" : "=l"(d) : "f"(lo), "f"(hi)); return d;
}
__device__ __forceinline__ void unpack2(u64 v, float &lo, float &hi) {
    asm("mov.b64 {%0, %1}, %2;" : "=f"(lo), "=f"(hi) : "l"(v));
}

// tanh via ex2/rcp approx: rel err ~1e-6, proven rel_err=3.9e-7 end-to-end in R1.
__device__ __forceinline__ float fast_tanh(float v) {
    const float n2log2e = -2.885390081777927f;  // -2*log2(e)
    float ax = fabsf(v), e, r;
    asm("ex2.approx.f32 %0, %1;" : "=f"(e) : "f"(ax * n2log2e));
    asm("rcp.approx.f32 %0, %1;" : "=f"(r) : "f"(1.0f + e));
    return copysignf((1.0f - e) * r, v);
}

__global__ __launch_bounds__(CTA_THREADS, 6)
void rnn_fwd_kernel(const float* __restrict__ x,
                    const float* __restrict__ Wxh,
                    const float* __restrict__ b_xh,
                    const float* __restrict__ Whh,
                    const float* __restrict__ b_hh,
                    const float* __restrict__ Wout,
                    const float* __restrict__ b_out,
                    float* __restrict__ out)
{
    __shared__ __align__(16) float sW[RNN_H * RNN_H];   // Whh[k][j], row-major
    __shared__ float sX[BATCH_PER_CTA][TT + 1];         // padded rows

    const int tid     = threadIdx.x;
    const int part    = tid & 3;          // which 8-wide j-slice this thread owns
    const int local_b = tid >> 2;         // batch row within CTA
    const int b       = blockIdx.x * BATCH_PER_CTA + local_b;
    const int j0      = part * 8;         // my output columns [j0, j0+8)

    // ---- stage Whh into smem ----
    #pragma unroll
    for (int i = tid; i < RNN_H * RNN_H; i += CTA_THREADS) sW[i] = Whh[i];

    // ---- per-thread constants in registers (my 8 columns) ----
    u64 bsum2[4], wxh2[4];
    #pragma unroll
    for (int m = 0; m < 4; m++) {
        int j = j0 + 2 * m;
        bsum2[m] = pack2(b_xh[j] + b_hh[j], b_xh[j + 1] + b_hh[j + 1]);
        wxh2[m]  = pack2(Wxh[j], Wxh[j + 1]);
    }

    // W row pointers for each shuffle-group g: rows 8*(part^g)+i, my column slice.
    const float* wptr[4];
    #pragma unroll
    for (int g = 0; g < 4; g++)
        wptr[g] = sW + (size_t)((part ^ g) * 8) * RNN_H + j0;

    // seg[g][i] = h value of unit k = 8*(part^g) + i
    float seg[4][8];
    #pragma unroll
    for (int g = 0; g < 4; g++)
        #pragma unroll
        for (int i = 0; i < 8; i++) seg[g][i] = 0.0f;

    const float* __restrict__ xbase = x + (size_t)(blockIdx.x * BATCH_PER_CTA) * RNN_T;

    for (int t0 = 0; t0 < RNN_T; t0 += TT) {
        __syncthreads();
        #pragma unroll
        for (int i = tid; i < BATCH_PER_CTA * TT; i += CTA_THREADS) {
            int bl = i >> 5, tt = i & (TT - 1);
            sX[bl][tt] = xbase[(size_t)bl * RNN_T + t0 + tt];
        }
        __syncthreads();

        #pragma unroll 1
        for (int tt = 0; tt < TT; tt++) {
            // acc[j0..j0+8) = bsum + x_t * Wxh
            float xv = sX[local_b][tt];            // 4-lane broadcast
            u64 xx = bcast2(xv);
            u64 acc[4];
            #pragma unroll
            for (int m = 0; m < 4; m++) {
                acc[m] = bsum2[m];
                fma2(acc[m], xx, wxh2[m]);
            }

            // acc += sum_k h_k * Whh[k][j],   k grouped by owner part (p^g)
            #pragma unroll
            for (int g = 0; g < 4; g++) {
                const float* wp = wptr[g];
                #pragma unroll
                for (int i = 0; i < 8; i++) {
                    u64 hk = bcast2(seg[g][i]);
                    ulonglong2 w0 = *reinterpret_cast<const ulonglong2*>(wp + i * RNN_H);
                    ulonglong2 w1 = *reinterpret_cast<const ulonglong2*>(wp + i * RNN_H + 4);
                    fma2(acc[0], hk, w0.x);
                    fma2(acc[1], hk, w0.y);
                    fma2(acc[2], hk, w1.x);
                    fma2(acc[3], hk, w1.y);
                }
            }

            // my 8 new h values
            #pragma unroll
            for (int m = 0; m < 4; m++) {
                float lo, hi;
                unpack2(acc[m], lo, hi);
                seg[0][2 * m]     = fast_tanh(lo);
                seg[0][2 * m + 1] = fast_tanh(hi);
            }

            // butterfly exchange within the 4-lane group:
            // seg1 <- part^1, seg2 <- part^2, seg3 <- part^3
            #pragma unroll
            for (int i = 0; i < 8; i++)
                seg[1][i] = __shfl_xor_sync(0xFFFFFFFFu, seg[0][i], 1);
            #pragma unroll
            for (int i = 0; i < 8; i++) {
                seg[2][i] = __shfl_xor_sync(0xFFFFFFFFu, seg[0][i], 2);
                seg[3][i] = __shfl_xor_sync(0xFFFFFFFFu, seg[1][i], 2);
            }
        }
    }

    // ---- epilogue: out[b] = h . Wout + b_out (4-lane reduction) ----
    float o = 0.0f;
    #pragma unroll
    for (int i = 0; i < 8; i++) o = fmaf(seg[0][i], Wout[j0 + i], o);
    o += __shfl_xor_sync(0xFFFFFFFFu, o, 1);
    o += __shfl_xor_sync(0xFFFFFFFFu, o, 2);
    if (part == 0) out[b] = o + b_out[0];
}

extern "C" void kernel_launch(void* const* d_in, const int* in_sizes, int n_in,
                              void* d_out, int out_size)
{
    const float* x     = (const float*)d_in[0];
    const float* Wxh   = (const float*)d_in[1];
    const float* b_xh  = (const float*)d_in[2];
    const float* Whh   = (const float*)d_in[3];
    const float* b_hh  = (const float*)d_in[4];
    const float* Wout  = (const float*)d_in[5];
    const float* b_out = (const float*)d_in[6];
    float* out = (float*)d_out;

    dim3 grid(RNN_B / BATCH_PER_CTA);   // 1024 CTAs
    dim3 blk(CTA_THREADS);              // 64 threads = 16 batches x 4 parts
    rnn_fwd_kernel<<<grid, blk>>>(x, Wxh, b_xh, Whh, b_hh, Wout, b_out, out);
}

// round 4
// speedup vs baseline: 10.9022x; 5.8212x over previous
#include <cuda_runtime.h>
#include <cuda_fp16.h>
#include <cstdint>

// RNN_49684181680264 : Elman RNN forward, B=16384, T=1024, H=32.
//   h_t = tanh(h_{t-1} @ Whh + b_hh + x_t * Wxh + b_xh);  out = h_T @ Wout + b_out
//
// R4: warp-level mma.sync HMMA (tcgen05 is rejected by this harness's ptxas
// target sm_103 -- no 'a' feature). One warp owns 16 batch rows. Whh is held
// PERMANENTLY in registers as B fragments (read once, never again -> kills the
// R2 LDS wall). fp32 via 2-way f16 split: D = Ahi*Bhi + Ahi*Blo + Alo*Bhi
// (3 passes, 24 HMMA/step/warp), fp32 accumulators. Bias + x*Wxh seed the
// accumulator. The m16n8k16 D fragment layout == A fragment layout needed next
// step, so the recurrence runs entirely in registers: no shuffles, no smem
// h-exchange, no barriers.

#define RNN_T 1024
#define RNN_H 32
#define ROWS_PER_CTA 16
#define TT 32

typedef uint32_t u32;

// tanh via ex2/rcp approx: rel err ~1e-6 (proven 4e-7 end-to-end in R1/R2).
__device__ __forceinline__ float fast_tanh(float v) {
    const float n2log2e = -2.885390081777927f;  // -2*log2(e)
    float ax = fabsf(v), e, r;
    asm("ex2.approx.f32 %0, %1;" : "=f"(e) : "f"(ax * n2log2e));
    asm("rcp.approx.f32 %0, %1;" : "=f"(r) : "f"(1.0f + e));
    return copysignf((1.0f - e) * r, v);
}

// pack two floats into f16x2: low half = lo, high half = hi (first src -> upper)
__device__ __forceinline__ u32 pack_half2(float lo, float hi) {
    u32 d;
    asm("cvt.rn.f16x2.f32 %0, %1, %2;" : "=r"(d) : "f"(hi), "f"(lo));
    return d;
}

// split (v0,v1) into f16 hi pair + f16 residual-lo pair
__device__ __forceinline__ void split_pair(float v0, float v1, u32 &hi, u32 &lo) {
    hi = pack_half2(v0, v1);
    __half2 h2 = *reinterpret_cast<const __half2*>(&hi);
    float f0 = __low2float(h2);
    float f1 = __high2float(h2);
    lo = pack_half2(v0 - f0, v1 - f1);
}

__device__ __forceinline__ void mma16816(float d[4], const u32 a[4], u32 b0, u32 b1) {
    asm volatile(
        "mma.sync.aligned.m16n8k16.row.col.f32.f16.f16.f32 "
        "{%0,%1,%2,%3}, {%4,%5,%6,%7}, {%8,%9}, {%0,%1,%2,%3};"
        : "+f"(d[0]), "+f"(d[1]), "+f"(d[2]), "+f"(d[3])
        : "r"(a[0]), "r"(a[1]), "r"(a[2]), "r"(a[3]), "r"(b0), "r"(b1));
}

__global__ __launch_bounds__(32)
void rnn_mma_kernel(const float* __restrict__ x,
                    const float* __restrict__ Wxh,
                    const float* __restrict__ b_xh,
                    const float* __restrict__ Whh,
                    const float* __restrict__ b_hh,
                    const float* __restrict__ Wout,
                    const float* __restrict__ b_out,
                    float* __restrict__ out)
{
    __shared__ float sX[ROWS_PER_CTA][TT + 1];   // x tile, padded rows

    const int lane = threadIdx.x;
    const int b0   = blockIdx.x * ROWS_PER_CTA;
    const int qr   = lane >> 2;          // row base within 16-row tile (0..7)
    const int qc   = (lane & 3) * 2;     // col pair base (0,2,4,6)

    // ---- B fragments: Whh[k][n], split f16 hi/lo, resident in registers ----
    // ntile j: n = 8j + qr ; ktile kt, reg r: k = 16kt + 8r + qc (+1)
    u32 Bhi[4][2][2], Blo[4][2][2];
    #pragma unroll
    for (int j = 0; j < 4; j++)
        #pragma unroll
        for (int kt = 0; kt < 2; kt++)
            #pragma unroll
            for (int r = 0; r < 2; r++) {
                int n = 8 * j + qr;
                int k = 16 * kt + 8 * r + qc;
                float w0 = Whh[k * RNN_H + n];
                float w1 = Whh[(k + 1) * RNN_H + n];
                split_pair(w0, w1, Bhi[j][kt][r], Blo[j][kt][r]);
            }

    // ---- per-thread column constants: cols c(j,e) = 8j + qc + e ----
    float wxh[8], bs[8], wo[8];
    #pragma unroll
    for (int j = 0; j < 4; j++)
        #pragma unroll
        for (int e = 0; e < 2; e++) {
            int c = 8 * j + qc + e;
            wxh[2 * j + e] = Wxh[c];
            bs[2 * j + e]  = b_xh[c] + b_hh[c];
            wo[2 * j + e]  = Wout[c];
        }

    // ---- A fragments (h state), start at h = 0 ----
    u32 Ahi[2][4], Alo[2][4];
    #pragma unroll
    for (int kt = 0; kt < 2; kt++)
        #pragma unroll
        for (int r = 0; r < 4; r++) { Ahi[kt][r] = 0u; Alo[kt][r] = 0u; }

    float th[16];   // tanh'd D values, persists to epilogue

    for (int t0 = 0; t0 < RNN_T; t0 += TT) {
        __syncwarp();
        // stage x[16 rows][32 steps], coalesced along t
        #pragma unroll
        for (int i = lane; i < ROWS_PER_CTA * TT; i += 32) {
            int r = i >> 5, c = i & 31;
            sX[r][c] = x[(size_t)(b0 + r) * RNN_T + t0 + c];
        }
        __syncwarp();

        #pragma unroll 1
        for (int tt = 0; tt < TT; tt++) {
            float xv0 = sX[qr][tt];        // row qr
            float xv1 = sX[qr + 8][tt];    // row qr+8

            // seed accumulators: D = bias + x * Wxh
            float D[4][4];
            #pragma unroll
            for (int j = 0; j < 4; j++) {
                D[j][0] = fmaf(xv0, wxh[2 * j],     bs[2 * j]);
                D[j][1] = fmaf(xv0, wxh[2 * j + 1], bs[2 * j + 1]);
                D[j][2] = fmaf(xv1, wxh[2 * j],     bs[2 * j]);
                D[j][3] = fmaf(xv1, wxh[2 * j + 1], bs[2 * j + 1]);
            }

            // D += h @ Whh  (split: hi*hi + hi*lo + lo*hi)
            #pragma unroll
            for (int kt = 0; kt < 2; kt++)
                #pragma unroll
                for (int j = 0; j < 4; j++) {
                    mma16816(D[j], Ahi[kt], Bhi[j][kt][0], Bhi[j][kt][1]);
                    mma16816(D[j], Ahi[kt], Blo[j][kt][0], Blo[j][kt][1]);
                    mma16816(D[j], Alo[kt], Bhi[j][kt][0], Bhi[j][kt][1]);
                }

            // h = tanh(D)
            #pragma unroll
            for (int i = 0; i < 16; i++)
                th[i] = fast_tanh(D[i >> 2][i & 3]);

            // rebuild A fragments from own th values (layout closure: no shfl)
            // Akt reg r: j = 2kt + (r>>1), element pair e = (r&1)*2
            #pragma unroll
            for (int kt = 0; kt < 2; kt++)
                #pragma unroll
                for (int r = 0; r < 4; r++) {
                    int j = 2 * kt + (r >> 1);
                    int e = (r & 1) * 2;
                    split_pair(th[4 * j + e], th[4 * j + e + 1],
                               Ahi[kt][r], Alo[kt][r]);
                }
        }
    }

    // ---- epilogue: out[b] = h . Wout + b_out ----
    float po0 = 0.0f, po1 = 0.0f;
    #pragma unroll
    for (int j = 0; j < 4; j++) {
        po0 = fmaf(th[4 * j],     wo[2 * j],     po0);
        po0 = fmaf(th[4 * j + 1], wo[2 * j + 1], po0);
        po1 = fmaf(th[4 * j + 2], wo[2 * j],     po1);
        po1 = fmaf(th[4 * j + 3], wo[2 * j + 1], po1);
    }
    po0 += __shfl_xor_sync(0xFFFFFFFFu, po0, 1);
    po0 += __shfl_xor_sync(0xFFFFFFFFu, po0, 2);
    po1 += __shfl_xor_sync(0xFFFFFFFFu, po1, 1);
    po1 += __shfl_xor_sync(0xFFFFFFFFu, po1, 2);
    if ((lane & 3) == 0) {
        float bo = b_out[0];
        out[b0 + qr]     = po0 + bo;
        out[b0 + qr + 8] = po1 + bo;
    }
}

extern "C" void kernel_launch(void* const* d_in, const int* in_sizes, int n_in,
                              void* d_out, int out_size)
{
    const float* x     = (const float*)d_in[0];
    const float* Wxh   = (const float*)d_in[1];
    const float* b_xh  = (const float*)d_in[2];
    const float* Whh   = (const float*)d_in[3];
    const float* b_hh  = (const float*)d_in[4];
    const float* Wout  = (const float*)d_in[5];
    const float* b_out = (const float*)d_in[6];
    float* out = (float*)d_out;

    dim3 grid(16384 / ROWS_PER_CTA);   // 1024 CTAs, one warp each
    dim3 blk(32);
    rnn_mma_kernel<<<grid, blk>>>(x, Wxh, b_xh, Whh, b_hh, Wout, b_out, out);
}

// round 5
// speedup vs baseline: 11.1699x; 1.0245x over previous
#include <cuda_runtime.h>
#include <cuda_fp16.h>
#include <cstdint>

// RNN_49684181680264 : Elman RNN forward, B=16384, T=1024, H=32.
//   h_t = tanh(h_{t-1} @ Whh + b_hh + x_t * Wxh + b_xh);  out = h_T @ Wout + b_out
//
// R5: R4 was latency-bound (issue 42.7%, 1.75 warps/SMSP, pipes <25%).
// Split the N=32 output columns across 2 warps per 16-row batch tile ->
// 2048 warps (3.46/SMSP), half the per-warp work (12 HMMA, 8 tanh values).
// h halves exchanged per step via double-buffered SMEM (STS.64/LDS.64,
// pad-20 u64 rows = conflict-free) + one __syncthreads.
// MUFU cut 32->12/warp-step: rcp paired over 2 values (d0*d1 in (1,4], safe
// because e=exp(-2|a|)<=1). h hi/lo split via mantissa mask (LOP3, alu pipe).
// Same validated split-f16 MMA math as R4 (D = Ahi*Bhi + Ahi*Blo + Alo*Bhi).

#define RNN_T 1024
#define RNN_H 32
#define ROWS_PER_CTA 16
#define TT 32
#define HB_PAD 20   // u64 row stride: (8*row + 2*c) % 32 distinct -> conflict-free

typedef uint32_t u32;
typedef unsigned long long u64;

// pack two fp32 into f16x2 (v0 -> low half, v1 -> high half)
__device__ __forceinline__ u32 pack_half2(float v0, float v1) {
    u32 d;
    asm("cvt.rn.f16x2.f32 %0, %1, %2;" : "=r"(d) : "f"(v1), "f"(v0));
    return d;
}
// init-time split (proven in R4)
__device__ __forceinline__ void split_pair_init(float v0, float v1, u32 &hi, u32 &lo) {
    hi = pack_half2(v0, v1);
    __half2 h2 = *reinterpret_cast<const __half2*>(&hi);
    lo = pack_half2(v0 - __low2float(h2), v1 - __high2float(h2));
}
// truncate fp32 mantissa to 10 bits -> exactly f16-representable hi part
__device__ __forceinline__ float trunc_hi(float v) {
    return __int_as_float(__float_as_int(v) & 0xFFFFE000);
}
__device__ __forceinline__ void mma16816(float d[4], const u32 a[4], u32 b0, u32 b1) {
    asm volatile(
        "mma.sync.aligned.m16n8k16.row.col.f32.f16.f16.f32 "
        "{%0,%1,%2,%3}, {%4,%5,%6,%7}, {%8,%9}, {%0,%1,%2,%3};"
        : "+f"(d[0]), "+f"(d[1]), "+f"(d[2]), "+f"(d[3])
        : "r"(a[0]), "r"(a[1]), "r"(a[2]), "r"(a[3]), "r"(b0), "r"(b1));
}
// tanh of two values sharing one rcp:  t=(1-e)/(1+e)*sign, e=exp(-2|a|)
__device__ __forceinline__ void tanh2(float a0, float a1, float &t0, float &t1) {
    const float c = -2.885390081777927f;  // -2*log2(e)
    float e0, e1, rp;
    asm("ex2.approx.f32 %0, %1;" : "=f"(e0) : "f"(fabsf(a0) * c));
    asm("ex2.approx.f32 %0, %1;" : "=f"(e1) : "f"(fabsf(a1) * c));
    float d0 = 1.0f + e0, d1 = 1.0f + e1;
    asm("rcp.approx.f32 %0, %1;" : "=f"(rp) : "f"(d0 * d1));
    t0 = copysignf((1.0f - e0) * (rp * d1), a0);
    t1 = copysignf((1.0f - e1) * (rp * d0), a1);
}

__global__ __launch_bounds__(64)
void rnn_mma2_kernel(const float* __restrict__ x,
                     const float* __restrict__ Wxh,
                     const float* __restrict__ b_xh,
                     const float* __restrict__ Whh,
                     const float* __restrict__ b_hh,
                     const float* __restrict__ Wout,
                     const float* __restrict__ b_out,
                     float* __restrict__ out)
{
    __shared__ float sX[ROWS_PER_CTA][TT + 1];
    __shared__ u64 hbuf[2][16][HB_PAD];    // [parity][row][colpair]: hi|lo<<32
    __shared__ float spart[2][16];

    const int tid  = threadIdx.x;
    const int lane = tid & 31;
    const int w    = tid >> 5;             // which n-half this warp owns
    const int qr   = lane >> 2;
    const int qc   = (lane & 3) * 2;
    const int b0   = blockIdx.x * ROWS_PER_CTA;

    // ---- B fragments (register-resident): j in {0,1}: n = 16w+8j+qr, k = 16kt+8r+qc ----
    u32 Bhi[2][2][2], Blo[2][2][2];
    #pragma unroll
    for (int j = 0; j < 2; j++)
        #pragma unroll
        for (int kt = 0; kt < 2; kt++)
            #pragma unroll
            for (int r = 0; r < 2; r++) {
                int n = 16 * w + 8 * j + qr;
                int k = 16 * kt + 8 * r + qc;
                split_pair_init(Whh[k * RNN_H + n], Whh[(k + 1) * RNN_H + n],
                                Bhi[j][kt][r], Blo[j][kt][r]);
            }

    // ---- per-thread column constants: col = 16w + 8j + qc + e ----
    float wxh[4], bs[4], wo[4];
    #pragma unroll
    for (int j = 0; j < 2; j++)
        #pragma unroll
        for (int e = 0; e < 2; e++) {
            int c = 16 * w + 8 * j + qc + e;
            wxh[2 * j + e] = Wxh[c];
            bs[2 * j + e]  = b_xh[c] + b_hh[c];
            wo[2 * j + e]  = Wout[c];
        }

    // ---- A fragments (h state), h = 0 ----
    u32 Ahi[2][4], Alo[2][4];
    #pragma unroll
    for (int kt = 0; kt < 2; kt++)
        #pragma unroll
        for (int r = 0; r < 4; r++) { Ahi[kt][r] = 0u; Alo[kt][r] = 0u; }

    float th[2][4];

    #pragma unroll 1
    for (int t = 0; t < RNN_T; t++) {
        const int tt = t & (TT - 1);
        if (tt == 0) {
            __syncthreads();   // prior tile's sX reads are done
            #pragma unroll
            for (int i = tid; i < ROWS_PER_CTA * TT; i += 64) {
                int r = i >> 5, c = i & 31;
                sX[r][c] = x[(size_t)(b0 + r) * RNN_T + t + c];
            }
            __syncthreads();
        }

        float xv0 = sX[qr][tt];
        float xv1 = sX[qr + 8][tt];

        // seed: D = bias + x * Wxh
        float D[2][4];
        #pragma unroll
        for (int j = 0; j < 2; j++) {
            D[j][0] = fmaf(xv0, wxh[2 * j],     bs[2 * j]);
            D[j][1] = fmaf(xv0, wxh[2 * j + 1], bs[2 * j + 1]);
            D[j][2] = fmaf(xv1, wxh[2 * j],     bs[2 * j]);
            D[j][3] = fmaf(xv1, wxh[2 * j + 1], bs[2 * j + 1]);
        }

        // D += h @ Whh (split passes)
        #pragma unroll
        for (int kt = 0; kt < 2; kt++)
            #pragma unroll
            for (int j = 0; j < 2; j++) {
                mma16816(D[j], Ahi[kt], Bhi[j][kt][0], Bhi[j][kt][1]);
                mma16816(D[j], Ahi[kt], Blo[j][kt][0], Blo[j][kt][1]);
                mma16816(D[j], Alo[kt], Bhi[j][kt][0], Bhi[j][kt][1]);
            }

        // tanh + hi/lo pack + store my n-half to the exchange buffer
        const int p = t & 1;
        #pragma unroll
        for (int j = 0; j < 2; j++) {
            float t0, t1, t2, t3;
            tanh2(D[j][0], D[j][1], t0, t1);
            tanh2(D[j][2], D[j][3], t2, t3);
            th[j][0] = t0; th[j][1] = t1; th[j][2] = t2; th[j][3] = t3;

            float h0 = trunc_hi(t0), h1 = trunc_hi(t1);
            u32 hip = pack_half2(h0, h1);
            u32 lop = pack_half2(t0 - h0, t1 - h1);
            hbuf[p][qr][8 * w + 4 * j + (lane & 3)] = (u64)hip | ((u64)lop << 32);

            h0 = trunc_hi(t2); h1 = trunc_hi(t3);
            hip = pack_half2(h0, h1);
            lop = pack_half2(t2 - h0, t3 - h1);
            hbuf[p][qr + 8][8 * w + 4 * j + (lane & 3)] = (u64)hip | ((u64)lop << 32);
        }
        __syncthreads();

        // rebuild full-K A fragments from both halves
        if (t < RNN_T - 1) {
            #pragma unroll
            for (int kt = 0; kt < 2; kt++)
                #pragma unroll
                for (int r = 0; r < 4; r++) {
                    u64 v = hbuf[p][qr + 8 * (r & 1)]
                                   [8 * kt + 4 * (r >> 1) + (lane & 3)];
                    Ahi[kt][r] = (u32)v;
                    Alo[kt][r] = (u32)(v >> 32);
                }
        }
    }

    // ---- epilogue: out[b] = h . Wout + b_out ----
    float po0 = 0.0f, po1 = 0.0f;
    #pragma unroll
    for (int j = 0; j < 2; j++) {
        po0 = fmaf(th[j][0], wo[2 * j],     po0);
        po0 = fmaf(th[j][1], wo[2 * j + 1], po0);
        po1 = fmaf(th[j][2], wo[2 * j],     po1);
        po1 = fmaf(th[j][3], wo[2 * j + 1], po1);
    }
    po0 += __shfl_xor_sync(0xFFFFFFFFu, po0, 1);
    po0 += __shfl_xor_sync(0xFFFFFFFFu, po0, 2);
    po1 += __shfl_xor_sync(0xFFFFFFFFu, po1, 1);
    po1 += __shfl_xor_sync(0xFFFFFFFFu, po1, 2);
    if ((lane & 3) == 0) {
        spart[w][qr]     = po0;
        spart[w][qr + 8] = po1;
    }
    __syncthreads();
    if (tid < 16)
        out[b0 + tid] = spart[0][tid] + spart[1][tid] + b_out[0];
}

extern "C" void kernel_launch(void* const* d_in, const int* in_sizes, int n_in,
                              void* d_out, int out_size)
{
    const float* x     = (const float*)d_in[0];
    const float* Wxh   = (const float*)d_in[1];
    const float* b_xh  = (const float*)d_in[2];
    const float* Whh   = (const float*)d_in[3];
    const float* b_hh  = (const float*)d_in[4];
    const float* Wout  = (const float*)d_in[5];
    const float* b_out = (const float*)d_in[6];
    float* out = (float*)d_out;

    dim3 grid(16384 / ROWS_PER_CTA);   // 1024 CTAs
    dim3 blk(64);                      // 2 warps: n-halves of one 16-row tile
    rnn_mma2_kernel<<<grid, blk>>>(x, Wxh, b_xh, Whh, b_hh, Wout, b_out, out);
}

// round 6
// speedup vs baseline: 13.5023x; 1.2088x over previous
#include <cuda_runtime.h>
#include <cuda_fp16.h>
#include <cstdint>

// RNN_49684181680264 : Elman RNN forward, B=16384, T=1024, H=32.
//   h_t = tanh(h_{t-1} @ Whh + b_hh + x_t * Wxh + b_xh);  out = h_T @ Wout + b_out
//
// R6: R4/R5 post-mortem showed the binding constraint is the SERIAL chain of
// 6 HMMAs accumulating into one D register (~150cyc each => ~900 of the
// ~1300cyc step wall). This round: R4's exchange-free single-warp layout
// (no barriers, no smem h-traffic) + each n-tile's 6 MMAs split into TWO
// independent 3-chains (A: seeded, B: zero), summed with 4 FADDs at the end.
// tanh via paired-rcp tanh2 (24 MUFU/step vs 32), sign reattached with one
// LOP3, and the A-fragment hi/lo split via mantissa-mask (LOP3) instead of
// f16 cvt round-trips. Same validated split-f16 math: D = Ahi*Bhi + Ahi*Blo
// + Alo*Bhi, fp32 accumulation.

#define RNN_T 1024
#define RNN_H 32
#define ROWS_PER_CTA 16
#define TT 32

typedef uint32_t u32;

// pack two fp32 into f16x2 (v0 -> low half, v1 -> high half)
__device__ __forceinline__ u32 pack_half2(float v0, float v1) {
    u32 d;
    asm("cvt.rn.f16x2.f32 %0, %1, %2;" : "=r"(d) : "f"(v1), "f"(v0));
    return d;
}
// init-time split (exact residual via cvt round-trip)
__device__ __forceinline__ void split_pair_init(float v0, float v1, u32 &hi, u32 &lo) {
    hi = pack_half2(v0, v1);
    __half2 h2 = *reinterpret_cast<const __half2*>(&hi);
    lo = pack_half2(v0 - __low2float(h2), v1 - __high2float(h2));
}
// truncate fp32 mantissa to 10 bits -> exactly f16-representable (|v|<2, no denorm issues)
__device__ __forceinline__ float trunc_hi(float v) {
    return __int_as_float(__float_as_int(v) & 0xFFFFE000);
}
__device__ __forceinline__ void mma16816(float d[4], const u32 a[4], u32 b0, u32 b1) {
    asm volatile(
        "mma.sync.aligned.m16n8k16.row.col.f32.f16.f16.f32 "
        "{%0,%1,%2,%3}, {%4,%5,%6,%7}, {%8,%9}, {%0,%1,%2,%3};"
        : "+f"(d[0]), "+f"(d[1]), "+f"(d[2]), "+f"(d[3])
        : "r"(a[0]), "r"(a[1]), "r"(a[2]), "r"(a[3]), "r"(b0), "r"(b1));
}
// tanh of two values sharing one rcp: t=(1-e)/(1+e), e=exp(-2|a|); sign via LOP3.
__device__ __forceinline__ void tanh2(float a0, float a1, float &t0, float &t1) {
    const float c = -2.885390081777927f;  // -2*log2(e)
    float e0, e1, rp;
    asm("ex2.approx.f32 %0, %1;" : "=f"(e0) : "f"(fabsf(a0) * c));
    asm("ex2.approx.f32 %0, %1;" : "=f"(e1) : "f"(fabsf(a1) * c));
    float d0 = 1.0f + e0, d1 = 1.0f + e1;
    asm("rcp.approx.f32 %0, %1;" : "=f"(rp) : "f"(d0 * d1));   // d0*d1 in (1,4]
    float m0 = (1.0f - e0) * (rp * d1);   // >= 0
    float m1 = (1.0f - e1) * (rp * d0);
    t0 = __int_as_float(__float_as_int(m0) | (__float_as_int(a0) & 0x80000000u));
    t1 = __int_as_float(__float_as_int(m1) | (__float_as_int(a1) & 0x80000000u));
}

__global__ __launch_bounds__(32)
void rnn_mma_kernel(const float* __restrict__ x,
                    const float* __restrict__ Wxh,
                    const float* __restrict__ b_xh,
                    const float* __restrict__ Whh,
                    const float* __restrict__ b_hh,
                    const float* __restrict__ Wout,
                    const float* __restrict__ b_out,
                    float* __restrict__ out)
{
    __shared__ float sX[ROWS_PER_CTA][TT + 1];

    const int lane = threadIdx.x;
    const int b0   = blockIdx.x * ROWS_PER_CTA;
    const int qr   = lane >> 2;
    const int qc   = (lane & 3) * 2;

    // ---- B fragments (register-resident, split f16 hi/lo) ----
    u32 Bhi[4][2][2], Blo[4][2][2];
    #pragma unroll
    for (int j = 0; j < 4; j++)
        #pragma unroll
        for (int kt = 0; kt < 2; kt++)
            #pragma unroll
            for (int r = 0; r < 2; r++) {
                int n = 8 * j + qr;
                int k = 16 * kt + 8 * r + qc;
                split_pair_init(Whh[k * RNN_H + n], Whh[(k + 1) * RNN_H + n],
                                Bhi[j][kt][r], Blo[j][kt][r]);
            }

    // ---- per-thread column constants: cols 8j + qc + e ----
    float wxh[8], bs[8], wo[8];
    #pragma unroll
    for (int j = 0; j < 4; j++)
        #pragma unroll
        for (int e = 0; e < 2; e++) {
            int c = 8 * j + qc + e;
            wxh[2 * j + e] = Wxh[c];
            bs[2 * j + e]  = b_xh[c] + b_hh[c];
            wo[2 * j + e]  = Wout[c];
        }

    // ---- A fragments (h state), h = 0 ----
    u32 Ahi[2][4], Alo[2][4];
    #pragma unroll
    for (int kt = 0; kt < 2; kt++)
        #pragma unroll
        for (int r = 0; r < 4; r++) { Ahi[kt][r] = 0u; Alo[kt][r] = 0u; }

    float th[16];

    for (int t0 = 0; t0 < RNN_T; t0 += TT) {
        __syncwarp();
        #pragma unroll
        for (int i = lane; i < ROWS_PER_CTA * TT; i += 32) {
            int r = i >> 5, c = i & 31;
            sX[r][c] = x[(size_t)(b0 + r) * RNN_T + t0 + c];
        }
        __syncwarp();

        #pragma unroll 1
        for (int tt = 0; tt < TT; tt++) {
            float xv0 = sX[qr][tt];
            float xv1 = sX[qr + 8][tt];

            // chain A accumulators: seeded with bias + x*Wxh
            float DA[4][4];
            #pragma unroll
            for (int j = 0; j < 4; j++) {
                DA[j][0] = fmaf(xv0, wxh[2 * j],     bs[2 * j]);
                DA[j][1] = fmaf(xv0, wxh[2 * j + 1], bs[2 * j + 1]);
                DA[j][2] = fmaf(xv1, wxh[2 * j],     bs[2 * j]);
                DA[j][3] = fmaf(xv1, wxh[2 * j + 1], bs[2 * j + 1]);
            }
            // chain B accumulators: zero
            float DB[4][4];
            #pragma unroll
            for (int j = 0; j < 4; j++)
                #pragma unroll
                for (int e = 0; e < 4; e++) DB[j][e] = 0.0f;

            // 6 MMAs per j, split into two INDEPENDENT 3-chains:
            //   A: (Ahi,Bhi,kt0) -> (Ahi,Bhi,kt1) -> (Ahi,Blo,kt0)
            //   B: (Ahi,Blo,kt1) -> (Alo,Bhi,kt0) -> (Alo,Bhi,kt1)
            #pragma unroll
            for (int j = 0; j < 4; j++) {
                mma16816(DA[j], Ahi[0], Bhi[j][0][0], Bhi[j][0][1]);
                mma16816(DB[j], Ahi[1], Blo[j][1][0], Blo[j][1][1]);
                mma16816(DA[j], Ahi[1], Bhi[j][1][0], Bhi[j][1][1]);
                mma16816(DB[j], Alo[0], Bhi[j][0][0], Bhi[j][0][1]);
                mma16816(DA[j], Ahi[0], Blo[j][0][0], Blo[j][0][1]);
                mma16816(DB[j], Alo[1], Bhi[j][1][0], Bhi[j][1][1]);
            }

            // h = tanh(DA + DB)
            #pragma unroll
            for (int j = 0; j < 4; j++) {
                tanh2(DA[j][0] + DB[j][0], DA[j][1] + DB[j][1],
                      th[4 * j],     th[4 * j + 1]);
                tanh2(DA[j][2] + DB[j][2], DA[j][3] + DB[j][3],
                      th[4 * j + 2], th[4 * j + 3]);
            }

            // rebuild A fragments (layout closure, mantissa-mask split)
            #pragma unroll
            for (int kt = 0; kt < 2; kt++)
                #pragma unroll
                for (int r = 0; r < 4; r++) {
                    int j = 2 * kt + (r >> 1);
                    int e = (r & 1) * 2;
                    float v0 = th[4 * j + e], v1 = th[4 * j + e + 1];
                    float h0 = trunc_hi(v0), h1 = trunc_hi(v1);
                    Ahi[kt][r] = pack_half2(h0, h1);
                    Alo[kt][r] = pack_half2(v0 - h0, v1 - h1);
                }
        }
    }

    // ---- epilogue: out[b] = h . Wout + b_out ----
    float po0 = 0.0f, po1 = 0.0f;
    #pragma unroll
    for (int j = 0; j < 4; j++) {
        po0 = fmaf(th[4 * j],     wo[2 * j],     po0);
        po0 = fmaf(th[4 * j + 1], wo[2 * j + 1], po0);
        po1 = fmaf(th[4 * j + 2], wo[2 * j],     po1);
        po1 = fmaf(th[4 * j + 3], wo[2 * j + 1], po1);
    }
    po0 += __shfl_xor_sync(0xFFFFFFFFu, po0, 1);
    po0 += __shfl_xor_sync(0xFFFFFFFFu, po0, 2);
    po1 += __shfl_xor_sync(0xFFFFFFFFu, po1, 1);
    po1 += __shfl_xor_sync(0xFFFFFFFFu, po1, 2);
    if ((lane & 3) == 0) {
        float bo = b_out[0];
        out[b0 + qr]     = po0 + bo;
        out[b0 + qr + 8] = po1 + bo;
    }
}

extern "C" void kernel_launch(void* const* d_in, const int* in_sizes, int n_in,
                              void* d_out, int out_size)
{
    const float* x     = (const float*)d_in[0];
    const float* Wxh   = (const float*)d_in[1];
    const float* b_xh  = (const float*)d_in[2];
    const float* Whh   = (const float*)d_in[3];
    const float* b_hh  = (const float*)d_in[4];
    const float* Wout  = (const float*)d_in[5];
    const float* b_out = (const float*)d_in[6];
    float* out = (float*)d_out;

    dim3 grid(16384 / ROWS_PER_CTA);   // 1024 CTAs, one warp each
    dim3 blk(32);
    rnn_mma_kernel<<<grid, blk>>>(x, Wxh, b_xh, Whh, b_hh, Wout, b_out, out);
}

// round 7
// speedup vs baseline: 23.6472x; 1.7513x over previous
#include <cuda_runtime.h>
#include <cuda_fp16.h>
#include <cstdint>

// RNN_49684181680264 : Elman RNN forward, B=16384, T=1024, H=32.
//   h_t = tanh(h_{t-1} @ Whh + b_hh + x_t * Wxh + b_xh);  out = h_T @ Wout + b_out
//
// R7 = R6 (register-resident split-f16 W, exchange-free fragment closure,
// dual independent 3-deep MMA chains) + two scalar-phase cuts:
//  1) tanh.approx.f32 (MUFU.TANH): 16 instr/step vs ~112 for the ex2/rcp trick.
//     Abs err ~2^-11/step; R1-R6 showed the recurrence is contractive
//     (1e-6 step error -> 5e-7 final), expect final rel_err ~1e-4..5e-4 < 1e-3.
//  2) chain-B's first MMA uses a persistent zero C operand (RZ) instead of
//     16 per-step zero MOVs.
// ~122 instr/step vs ~235 in R6.

#define RNN_T 1024
#define RNN_H 32
#define ROWS_PER_CTA 16
#define TT 32

typedef uint32_t u32;

// pack two fp32 into f16x2 (v0 -> low half, v1 -> high half)
__device__ __forceinline__ u32 pack_half2(float v0, float v1) {
    u32 d;
    asm("cvt.rn.f16x2.f32 %0, %1, %2;" : "=r"(d) : "f"(v1), "f"(v0));
    return d;
}
// init-time split (exact residual via cvt round-trip)
__device__ __forceinline__ void split_pair_init(float v0, float v1, u32 &hi, u32 &lo) {
    hi = pack_half2(v0, v1);
    __half2 h2 = *reinterpret_cast<const __half2*>(&hi);
    lo = pack_half2(v0 - __low2float(h2), v1 - __high2float(h2));
}
// truncate fp32 mantissa to 10 bits -> exactly f16-representable (|v|<1 here)
__device__ __forceinline__ float trunc_hi(float v) {
    return __int_as_float(__float_as_int(v) & 0xFFFFE000);
}
// accumulating MMA: D += A*B
__device__ __forceinline__ void mma16816(float d[4], const u32 a[4], u32 b0, u32 b1) {
    asm volatile(
        "mma.sync.aligned.m16n8k16.row.col.f32.f16.f16.f32 "
        "{%0,%1,%2,%3}, {%4,%5,%6,%7}, {%8,%9}, {%0,%1,%2,%3};"
        : "+f"(d[0]), "+f"(d[1]), "+f"(d[2]), "+f"(d[3])
        : "r"(a[0]), "r"(a[1]), "r"(a[2]), "r"(a[3]), "r"(b0), "r"(b1));
}
// chain-starting MMA: D = A*B + Z where Z is a persistent zero vector (RZ)
__device__ __forceinline__ void mma16816_z(float d[4], const u32 a[4], u32 b0, u32 b1,
                                           float z0, float z1, float z2, float z3) {
    asm volatile(
        "mma.sync.aligned.m16n8k16.row.col.f32.f16.f16.f32 "
        "{%0,%1,%2,%3}, {%4,%5,%6,%7}, {%8,%9}, {%10,%11,%12,%13};"
        : "=f"(d[0]), "=f"(d[1]), "=f"(d[2]), "=f"(d[3])
        : "r"(a[0]), "r"(a[1]), "r"(a[2]), "r"(a[3]), "r"(b0), "r"(b1),
          "f"(z0), "f"(z1), "f"(z2), "f"(z3));
}
__device__ __forceinline__ float tanh_mufu(float v) {
    float t;
    asm("tanh.approx.f32 %0, %1;" : "=f"(t) : "f"(v));
    return t;
}

__global__ __launch_bounds__(32)
void rnn_mma_kernel(const float* __restrict__ x,
                    const float* __restrict__ Wxh,
                    const float* __restrict__ b_xh,
                    const float* __restrict__ Whh,
                    const float* __restrict__ b_hh,
                    const float* __restrict__ Wout,
                    const float* __restrict__ b_out,
                    float* __restrict__ out)
{
    __shared__ float sX[ROWS_PER_CTA][TT + 1];

    const int lane = threadIdx.x;
    const int b0   = blockIdx.x * ROWS_PER_CTA;
    const int qr   = lane >> 2;
    const int qc   = (lane & 3) * 2;

    // ---- B fragments (register-resident, split f16 hi/lo) ----
    u32 Bhi[4][2][2], Blo[4][2][2];
    #pragma unroll
    for (int j = 0; j < 4; j++)
        #pragma unroll
        for (int kt = 0; kt < 2; kt++)
            #pragma unroll
            for (int r = 0; r < 2; r++) {
                int n = 8 * j + qr;
                int k = 16 * kt + 8 * r + qc;
                split_pair_init(Whh[k * RNN_H + n], Whh[(k + 1) * RNN_H + n],
                                Bhi[j][kt][r], Blo[j][kt][r]);
            }

    // ---- per-thread column constants: cols 8j + qc + e ----
    float wxh[8], bs[8], wo[8];
    #pragma unroll
    for (int j = 0; j < 4; j++)
        #pragma unroll
        for (int e = 0; e < 2; e++) {
            int c = 8 * j + qc + e;
            wxh[2 * j + e] = Wxh[c];
            bs[2 * j + e]  = b_xh[c] + b_hh[c];
            wo[2 * j + e]  = Wout[c];
        }

    // persistent zero C operand (ptxas -> RZ)
    const float fz = 0.0f;

    // ---- A fragments (h state), h = 0 ----
    u32 Ahi[2][4], Alo[2][4];
    #pragma unroll
    for (int kt = 0; kt < 2; kt++)
        #pragma unroll
        for (int r = 0; r < 4; r++) { Ahi[kt][r] = 0u; Alo[kt][r] = 0u; }

    float th[16];

    for (int t0 = 0; t0 < RNN_T; t0 += TT) {
        __syncwarp();
        #pragma unroll
        for (int i = lane; i < ROWS_PER_CTA * TT; i += 32) {
            int r = i >> 5, c = i & 31;
            sX[r][c] = x[(size_t)(b0 + r) * RNN_T + t0 + c];
        }
        __syncwarp();

        #pragma unroll 1
        for (int tt = 0; tt < TT; tt++) {
            float xv0 = sX[qr][tt];
            float xv1 = sX[qr + 8][tt];

            // chain A accumulators: seeded with bias + x*Wxh
            float DA[4][4];
            #pragma unroll
            for (int j = 0; j < 4; j++) {
                DA[j][0] = fmaf(xv0, wxh[2 * j],     bs[2 * j]);
                DA[j][1] = fmaf(xv0, wxh[2 * j + 1], bs[2 * j + 1]);
                DA[j][2] = fmaf(xv1, wxh[2 * j],     bs[2 * j]);
                DA[j][3] = fmaf(xv1, wxh[2 * j + 1], bs[2 * j + 1]);
            }
            float DB[4][4];

            // 6 MMAs per j in two INDEPENDENT 3-chains (B-chain starts from RZ):
            #pragma unroll
            for (int j = 0; j < 4; j++) {
                mma16816  (DA[j], Ahi[0], Bhi[j][0][0], Bhi[j][0][1]);
                mma16816_z(DB[j], Ahi[1], Blo[j][1][0], Blo[j][1][1], fz, fz, fz, fz);
                mma16816  (DA[j], Ahi[1], Bhi[j][1][0], Bhi[j][1][1]);
                mma16816  (DB[j], Alo[0], Bhi[j][0][0], Bhi[j][0][1]);
                mma16816  (DA[j], Ahi[0], Blo[j][0][0], Blo[j][0][1]);
                mma16816  (DB[j], Alo[1], Bhi[j][1][0], Bhi[j][1][1]);
            }

            // h = tanh(DA + DB)  -- MUFU.TANH
            #pragma unroll
            for (int j = 0; j < 4; j++) {
                th[4 * j]     = tanh_mufu(DA[j][0] + DB[j][0]);
                th[4 * j + 1] = tanh_mufu(DA[j][1] + DB[j][1]);
                th[4 * j + 2] = tanh_mufu(DA[j][2] + DB[j][2]);
                th[4 * j + 3] = tanh_mufu(DA[j][3] + DB[j][3]);
            }

            // rebuild A fragments (layout closure, mantissa-mask split)
            #pragma unroll
            for (int kt = 0; kt < 2; kt++)
                #pragma unroll
                for (int r = 0; r < 4; r++) {
                    int j = 2 * kt + (r >> 1);
                    int e = (r & 1) * 2;
                    float v0 = th[4 * j + e], v1 = th[4 * j + e + 1];
                    float h0 = trunc_hi(v0), h1 = trunc_hi(v1);
                    Ahi[kt][r] = pack_half2(h0, h1);
                    Alo[kt][r] = pack_half2(v0 - h0, v1 - h1);
                }
        }
    }

    // ---- epilogue: out[b] = h . Wout + b_out ----
    float po0 = 0.0f, po1 = 0.0f;
    #pragma unroll
    for (int j = 0; j < 4; j++) {
        po0 = fmaf(th[4 * j],     wo[2 * j],     po0);
        po0 = fmaf(th[4 * j + 1], wo[2 * j + 1], po0);
        po1 = fmaf(th[4 * j + 2], wo[2 * j],     po1);
        po1 = fmaf(th[4 * j + 3], wo[2 * j + 1], po1);
    }
    po0 += __shfl_xor_sync(0xFFFFFFFFu, po0, 1);
    po0 += __shfl_xor_sync(0xFFFFFFFFu, po0, 2);
    po1 += __shfl_xor_sync(0xFFFFFFFFu, po1, 1);
    po1 += __shfl_xor_sync(0xFFFFFFFFu, po1, 2);
    if ((lane & 3) == 0) {
        float bo = b_out[0];
        out[b0 + qr]     = po0 + bo;
        out[b0 + qr + 8] = po1 + bo;
    }
}

extern "C" void kernel_launch(void* const* d_in, const int* in_sizes, int n_in,
                              void* d_out, int out_size)
{
    const float* x     = (const float*)d_in[0];
    const float* Wxh   = (const float*)d_in[1];
    const float* b_xh  = (const float*)d_in[2];
    const float* Whh   = (const float*)d_in[3];
    const float* b_hh  = (const float*)d_in[4];
    const float* Wout  = (const float*)d_in[5];
    const float* b_out = (const float*)d_in[6];
    float* out = (float*)d_out;

    dim3 grid(16384 / ROWS_PER_CTA);   // 1024 CTAs, one warp each
    dim3 blk(32);
    rnn_mma_kernel<<<grid, blk>>>(x, Wxh, b_xh, Whh, b_hh, Wout, b_out, out);
}

// round 8
// speedup vs baseline: 27.9609x; 1.1824x over previous
#include <cuda_runtime.h>
#include <cuda_fp16.h>
#include <cstdint>

// RNN_49684181680264 : Elman RNN forward, B=16384, T=1024, H=32.
//   h_t = tanh(h_{t-1} @ Whh + b_hh + x_t * Wxh + b_xh);  out = h_T @ Wout + b_out
//
// R8 = R7 minus the A-lo MMA pass. R7 measured that a 2^-11-class per-step
// error (MUFU.TANH) costs only 1e-5 final rel_err -- the recurrence is
// strongly contractive. h's sub-f16 bits are the same 2^-11 class, so carry
// h in f16 only: D = Ahi*Bhi + Ahi*Blo  (W still exact as f16 hi+lo split).
// 16 HMMA/step (was 24), two independent 2-deep chains, repack = 8 cvt
// instructions (no trunc/sub/Alo). ~80 instr/step vs ~122.

#define RNN_T 1024
#define RNN_H 32
#define ROWS_PER_CTA 16
#define TT 32

typedef uint32_t u32;

// pack two fp32 into f16x2 (v0 -> low half, v1 -> high half)
__device__ __forceinline__ u32 pack_half2(float v0, float v1) {
    u32 d;
    asm("cvt.rn.f16x2.f32 %0, %1, %2;" : "=r"(d) : "f"(v1), "f"(v0));
    return d;
}
// init-time split (exact residual via cvt round-trip)
__device__ __forceinline__ void split_pair_init(float v0, float v1, u32 &hi, u32 &lo) {
    hi = pack_half2(v0, v1);
    __half2 h2 = *reinterpret_cast<const __half2*>(&hi);
    lo = pack_half2(v0 - __low2float(h2), v1 - __high2float(h2));
}
// accumulating MMA: D += A*B
__device__ __forceinline__ void mma16816(float d[4], const u32 a[4], u32 b0, u32 b1) {
    asm volatile(
        "mma.sync.aligned.m16n8k16.row.col.f32.f16.f16.f32 "
        "{%0,%1,%2,%3}, {%4,%5,%6,%7}, {%8,%9}, {%0,%1,%2,%3};"
        : "+f"(d[0]), "+f"(d[1]), "+f"(d[2]), "+f"(d[3])
        : "r"(a[0]), "r"(a[1]), "r"(a[2]), "r"(a[3]), "r"(b0), "r"(b1));
}
// chain-starting MMA: D = A*B + 0 (C from persistent zero regs -> RZ)
__device__ __forceinline__ void mma16816_z(float d[4], const u32 a[4], u32 b0, u32 b1,
                                           float z) {
    asm volatile(
        "mma.sync.aligned.m16n8k16.row.col.f32.f16.f16.f32 "
        "{%0,%1,%2,%3}, {%4,%5,%6,%7}, {%8,%9}, {%10,%10,%10,%10};"
        : "=f"(d[0]), "=f"(d[1]), "=f"(d[2]), "=f"(d[3])
        : "r"(a[0]), "r"(a[1]), "r"(a[2]), "r"(a[3]), "r"(b0), "r"(b1),
          "f"(z));
}
__device__ __forceinline__ float tanh_mufu(float v) {
    float t;
    asm("tanh.approx.f32 %0, %1;" : "=f"(t) : "f"(v));
    return t;
}

__global__ __launch_bounds__(32)
void rnn_mma_kernel(const float* __restrict__ x,
                    const float* __restrict__ Wxh,
                    const float* __restrict__ b_xh,
                    const float* __restrict__ Whh,
                    const float* __restrict__ b_hh,
                    const float* __restrict__ Wout,
                    const float* __restrict__ b_out,
                    float* __restrict__ out)
{
    __shared__ float sX[ROWS_PER_CTA][TT + 1];

    const int lane = threadIdx.x;
    const int b0   = blockIdx.x * ROWS_PER_CTA;
    const int qr   = lane >> 2;
    const int qc   = (lane & 3) * 2;

    // ---- B fragments (register-resident, split f16 hi/lo: W stays exact) ----
    u32 Bhi[4][2][2], Blo[4][2][2];
    #pragma unroll
    for (int j = 0; j < 4; j++)
        #pragma unroll
        for (int kt = 0; kt < 2; kt++)
            #pragma unroll
            for (int r = 0; r < 2; r++) {
                int n = 8 * j + qr;
                int k = 16 * kt + 8 * r + qc;
                split_pair_init(Whh[k * RNN_H + n], Whh[(k + 1) * RNN_H + n],
                                Bhi[j][kt][r], Blo[j][kt][r]);
            }

    // ---- per-thread column constants: cols 8j + qc + e ----
    float wxh[8], bs[8], wo[8];
    #pragma unroll
    for (int j = 0; j < 4; j++)
        #pragma unroll
        for (int e = 0; e < 2; e++) {
            int c = 8 * j + qc + e;
            wxh[2 * j + e] = Wxh[c];
            bs[2 * j + e]  = b_xh[c] + b_hh[c];
            wo[2 * j + e]  = Wout[c];
        }

    const float fz = 0.0f;   // persistent zero C operand

    // ---- A fragments (h state as f16), h = 0 ----
    u32 Ahi[2][4];
    #pragma unroll
    for (int kt = 0; kt < 2; kt++)
        #pragma unroll
        for (int r = 0; r < 4; r++) Ahi[kt][r] = 0u;

    float th[16];

    for (int t0 = 0; t0 < RNN_T; t0 += TT) {
        __syncwarp();
        #pragma unroll
        for (int i = lane; i < ROWS_PER_CTA * TT; i += 32) {
            int r = i >> 5, c = i & 31;
            sX[r][c] = x[(size_t)(b0 + r) * RNN_T + t0 + c];
        }
        __syncwarp();

        #pragma unroll 1
        for (int tt = 0; tt < TT; tt++) {
            float xv0 = sX[qr][tt];
            float xv1 = sX[qr + 8][tt];

            // chain A accumulators: seeded with bias + x*Wxh
            float DA[4][4];
            #pragma unroll
            for (int j = 0; j < 4; j++) {
                DA[j][0] = fmaf(xv0, wxh[2 * j],     bs[2 * j]);
                DA[j][1] = fmaf(xv0, wxh[2 * j + 1], bs[2 * j + 1]);
                DA[j][2] = fmaf(xv1, wxh[2 * j],     bs[2 * j]);
                DA[j][3] = fmaf(xv1, wxh[2 * j + 1], bs[2 * j + 1]);
            }
            float DB[4][4];

            // per j: 2 independent 2-deep chains
            //   A: (Ahi0, Bhi kt0) -> (Ahi1, Bhi kt1)   [seeded]
            //   B: (Ahi0, Blo kt0) -> (Ahi1, Blo kt1)   [zero-C start]
            #pragma unroll
            for (int j = 0; j < 4; j++) {
                mma16816  (DA[j], Ahi[0], Bhi[j][0][0], Bhi[j][0][1]);
                mma16816_z(DB[j], Ahi[0], Blo[j][0][0], Blo[j][0][1], fz);
                mma16816  (DA[j], Ahi[1], Bhi[j][1][0], Bhi[j][1][1]);
                mma16816  (DB[j], Ahi[1], Blo[j][1][0], Blo[j][1][1]);
            }

            // h = tanh(DA + DB)  -- MUFU.TANH
            #pragma unroll
            for (int j = 0; j < 4; j++) {
                th[4 * j]     = tanh_mufu(DA[j][0] + DB[j][0]);
                th[4 * j + 1] = tanh_mufu(DA[j][1] + DB[j][1]);
                th[4 * j + 2] = tanh_mufu(DA[j][2] + DB[j][2]);
                th[4 * j + 3] = tanh_mufu(DA[j][3] + DB[j][3]);
            }

            // rebuild A fragments: straight f16 pack (layout closure)
            #pragma unroll
            for (int kt = 0; kt < 2; kt++)
                #pragma unroll
                for (int r = 0; r < 4; r++) {
                    int j = 2 * kt + (r >> 1);
                    int e = (r & 1) * 2;
                    Ahi[kt][r] = pack_half2(th[4 * j + e], th[4 * j + e + 1]);
                }
        }
    }

    // ---- epilogue: out[b] = h . Wout + b_out ----
    float po0 = 0.0f, po1 = 0.0f;
    #pragma unroll
    for (int j = 0; j < 4; j++) {
        po0 = fmaf(th[4 * j],     wo[2 * j],     po0);
        po0 = fmaf(th[4 * j + 1], wo[2 * j + 1], po0);
        po1 = fmaf(th[4 * j + 2], wo[2 * j],     po1);
        po1 = fmaf(th[4 * j + 3], wo[2 * j + 1], po1);
    }
    po0 += __shfl_xor_sync(0xFFFFFFFFu, po0, 1);
    po0 += __shfl_xor_sync(0xFFFFFFFFu, po0, 2);
    po1 += __shfl_xor_sync(0xFFFFFFFFu, po1, 1);
    po1 += __shfl_xor_sync(0xFFFFFFFFu, po1, 2);
    if ((lane & 3) == 0) {
        float bo = b_out[0];
        out[b0 + qr]     = po0 + bo;
        out[b0 + qr + 8] = po1 + bo;
    }
}

extern "C" void kernel_launch(void* const* d_in, const int* in_sizes, int n_in,
                              void* d_out, int out_size)
{
    const float* x     = (const float*)d_in[0];
    const float* Wxh   = (const float*)d_in[1];
    const float* b_xh  = (const float*)d_in[2];
    const float* Whh   = (const float*)d_in[3];
    const float* b_hh  = (const float*)d_in[4];
    const float* Wout  = (const float*)d_in[5];
    const float* b_out = (const float*)d_in[6];
    float* out = (float*)d_out;

    dim3 grid(16384 / ROWS_PER_CTA);   // 1024 CTAs, one warp each
    dim3 blk(32);
    rnn_mma_kernel<<<grid, blk>>>(x, Wxh, b_xh, Whh, b_hh, Wout, b_out, out);
}